// round 14
// baseline (speedup 1.0000x reference)
#include <cuda_runtime.h>
#include <cuda_fp16.h>
#include <cstdint>

#define BATCH 4
#define CH    512
#define NPTS  4096
#define MROWS (BATCH * NPTS)   // 16384
#define KNN   5
#define KDIM  (2 * CH)         // 1024

// ================= PTX helpers (baseline ISA only — no sm_103a features) =========
__device__ __forceinline__ uint32_t smem_u32(const void* p) {
    return (uint32_t)__cvta_generic_to_shared((void*)p);
}
#define SWZ(o) ((o) ^ (((o) >> 3) & 0x70))

__device__ __forceinline__ void ldsm_x4(uint32_t (&r)[4], uint32_t addr) {
    asm volatile("ldmatrix.sync.aligned.m8n8.x4.shared.b16 {%0,%1,%2,%3}, [%4];"
                 : "=r"(r[0]), "=r"(r[1]), "=r"(r[2]), "=r"(r[3]) : "r"(addr));
}
__device__ __forceinline__ void ldsm_x2(uint32_t (&r)[2], uint32_t addr) {
    asm volatile("ldmatrix.sync.aligned.m8n8.x2.shared.b16 {%0,%1}, [%2];"
                 : "=r"(r[0]), "=r"(r[1]) : "r"(addr));
}
__device__ __forceinline__ void mma16816(float (&c)[4], const uint32_t (&a)[4],
                                         uint32_t b0, uint32_t b1) {
    asm volatile("mma.sync.aligned.m16n8k16.row.col.f32.f16.f16.f32 "
                 "{%0,%1,%2,%3}, {%4,%5,%6,%7}, {%8,%9}, {%0,%1,%2,%3};"
                 : "+f"(c[0]), "+f"(c[1]), "+f"(c[2]), "+f"(c[3])
                 : "r"(a[0]), "r"(a[1]), "r"(a[2]), "r"(a[3]), "r"(b0), "r"(b1));
}
#define CP_ASYNC16(dst, src) \
    asm volatile("cp.async.cg.shared.global [%0], [%1], 16;" :: "r"(dst), "l"(src))
#define CP_COMMIT() asm volatile("cp.async.commit_group;" ::: "memory")
#define CP_WAIT1()  asm volatile("cp.async.wait_group 1;" ::: "memory")
#define CP_WAIT0()  asm volatile("cp.async.wait_group 0;" ::: "memory")

// ================= scratch (static device globals; no allocation) =================
__device__ float g_xt[(size_t)MROWS * CH];
__device__ __align__(16) __half g_Ahi[(size_t)MROWS * KDIM];
__device__ __align__(16) __half g_Alo[(size_t)MROWS * KDIM];
__device__ __align__(16) __half g_Whi[(size_t)3 * CH * KDIM];
__device__ __align__(16) __half g_Chi[(size_t)(CH / 2) * CH];
__device__ float g_y[(size_t)MROWS * CH];
__device__ float g_h[(size_t)MROWS * (CH / 2)];
__device__ int   g_idx[MROWS * KNN];
__device__ __align__(16) float g_sum[3 * CH];     // per-layer column sums
__device__ __align__(16) float g_sumsq[3 * CH];

__device__ __forceinline__ uint32_t pack_pair(float s, float m, float& sl, float& ml) {
    __half2 v;
    v.x = __float2half_rn(s);
    v.y = __float2half_rn(m);
    sl = s - __half2float(v.x);
    ml = m - __half2float(v.y);
    return *(uint32_t*)&v;
}
__device__ __forceinline__ uint32_t pack_lo(float sl, float ml) {
    __half2 v;
    v.x = __float2half_rn(sl);
    v.y = __float2half_rn(ml);
    return *(uint32_t*)&v;
}

// ---------------- transpose: x [B,C,N] -> g_xt [B*N, C] ----------------
__global__ void transpose_kernel(const float* __restrict__ x) {
    __shared__ float tile[32][33];
    int b = blockIdx.z;
    int n0 = blockIdx.x * 32, c0 = blockIdx.y * 32;
    int tx = threadIdx.x, ty = threadIdx.y;
#pragma unroll
    for (int i = 0; i < 4; i++) {
        int c = c0 + ty + i * 8;
        tile[ty + i * 8][tx] = x[((size_t)(b * CH + c)) * NPTS + n0 + tx];
    }
    __syncthreads();
#pragma unroll
    for (int i = 0; i < 4; i++) {
        int n = n0 + ty + i * 8;
        g_xt[((size_t)(b * NPTS + n)) * CH + c0 + tx] = tile[tx][ty + i * 8];
    }
}

// ---------------- KNN (bit-exact vs reference; DO NOT TOUCH) ----------------
#define LTC(da, ia, db, ib) ((da) < (db) || ((da) == (db) && (ia) < (ib)))

__global__ void knn_kernel(const float* __restrict__ pos) {
    __shared__ float sx[NPTS];
    __shared__ float sy[NPTS];
    __shared__ float sd[NPTS];
    int b = blockIdx.y;
    const float* p = pos + (size_t)b * NPTS * 2;
    for (int j = threadIdx.x; j < NPTS; j += blockDim.x) {
        float xx = p[2 * j], yy = p[2 * j + 1];
        sx[j] = xx; sy[j] = yy;
        sd[j] = __fadd_rn(__fmul_rn(xx, xx), __fmul_rn(yy, yy));  // add-form d2
    }
    __syncthreads();

    int warp = threadIdx.x >> 5, lane = threadIdx.x & 31;
    int q = blockIdx.x * (blockDim.x >> 5) + warp;

    float xi = sx[q], yi = sy[q], d2i = sd[q];
    const float INF = __int_as_float(0x7f800000);
    float d0 = INF, d1 = INF, d2 = INF, d3 = INF, d4 = INF;
    int   i0 = 0x7fffffff, i1 = 0x7fffffff, i2 = 0x7fffffff, i3 = 0x7fffffff, i4 = 0x7fffffff;

    for (int j = lane; j < NPTS; j += 32) {
        float dot  = __fmaf_rn(yi, sy[j], __fmul_rn(xi, sx[j]));  // fma-form dot
        float dist = __fadd_rn(__fadd_rn(d2i, sd[j]), -__fmul_rn(2.0f, dot));
        if (LTC(dist, j, d4, i4)) {
            d4 = dist; i4 = j;
            if (LTC(d4, i4, d3, i3)) { float tf = d3; d3 = d4; d4 = tf; int ti = i3; i3 = i4; i4 = ti; }
            if (LTC(d3, i3, d2, i2)) { float tf = d2; d2 = d3; d3 = tf; int ti = i2; i2 = i3; i3 = ti; }
            if (LTC(d2, i2, d1, i1)) { float tf = d1; d1 = d2; d2 = tf; int ti = i1; i1 = i2; i2 = ti; }
            if (LTC(d1, i1, d0, i0)) { float tf = d0; d0 = d1; d1 = tf; int ti = i0; i0 = i1; i1 = ti; }
        }
    }
#pragma unroll
    for (int k = 0; k < KNN; k++) {
        float od = d0; int oi = i0;
#pragma unroll
        for (int off = 16; off; off >>= 1) {
            float td = __shfl_down_sync(0xffffffffu, od, off);
            int   ti = __shfl_down_sync(0xffffffffu, oi, off);
            if (LTC(td, ti, od, oi)) { od = td; oi = ti; }
        }
        od = __shfl_sync(0xffffffffu, od, 0);
        oi = __shfl_sync(0xffffffffu, oi, 0);
        if (oi == i0) {
            d0 = d1; i0 = i1; d1 = d2; i1 = i2; d2 = d3; i2 = i3; d3 = d4; i3 = i4;
            d4 = INF; i4 = 0x7fffffff;
        }
        if (lane == 0) g_idx[((size_t)(b * NPTS + q)) * KNN + k] = oi;
    }
}

// ---------------- feat (layer 1): 1 row per 128-thread block, float4 -------------
__global__ void feat_kernel() {
    __shared__ int nb[KNN];
    int r = blockIdx.x, tid = threadIdx.x;
    if (tid < KNN) nb[tid] = (r >> 12) * NPTS + g_idx[r * KNN + tid];
    __syncthreads();
    float4 s = ((const float4*)(g_xt + (size_t)r * CH))[tid];
    float4 m = make_float4(-1e30f, -1e30f, -1e30f, -1e30f);
#pragma unroll
    for (int k = 0; k < KNN; k++) {
        float4 v = ((const float4*)(g_xt + (size_t)nb[k] * CH))[tid];
        m.x = fmaxf(m.x, v.x - s.x); m.y = fmaxf(m.y, v.y - s.y);
        m.z = fmaxf(m.z, v.z - s.z); m.w = fmaxf(m.w, v.w - s.w);
    }
    float slx, mlx, sly, mly, slz, mlz, slw, mlw;
    uint4 hi, lo;
    hi.x = pack_pair(s.x, m.x, slx, mlx);
    hi.y = pack_pair(s.y, m.y, sly, mly);
    hi.z = pack_pair(s.z, m.z, slz, mlz);
    hi.w = pack_pair(s.w, m.w, slw, mlw);
    lo.x = pack_lo(slx, mlx); lo.y = pack_lo(sly, mly);
    lo.z = pack_lo(slz, mlz); lo.w = pack_lo(slw, mlw);
    ((uint4*)(g_Ahi + (size_t)r * KDIM))[tid] = hi;
    ((uint4*)(g_Alo + (size_t)r * KDIM))[tid] = lo;
}

// ---- bnfeat (layers 2,3): inline BN coefs from per-layer stats, gather+maxrel ----
__global__ void bnfeat_kernel(const float* __restrict__ gamma, const float* __restrict__ beta,
                              const float* __restrict__ gsum, const float* __restrict__ gsumsq) {
    __shared__ int nb[KNN];
    int r = blockIdx.x, tid = threadIdx.x;
    if (tid < KNN) nb[tid] = (r >> 12) * NPTS + g_idx[r * KNN + tid];
    __syncthreads();
    const float inv = 1.0f / (float)MROWS;
    float4 sm = ((const float4*)gsum)[tid];
    float4 sq = ((const float4*)gsumsq)[tid];
    float4 gm = ((const float4*)gamma)[tid];
    float4 bt = ((const float4*)beta)[tid];
    float4 a, b;
    {
        float mean;
        mean = sm.x * inv; a.x = rsqrtf(sq.x * inv - mean * mean + 1e-5f) * gm.x; b.x = bt.x - mean * a.x;
        mean = sm.y * inv; a.y = rsqrtf(sq.y * inv - mean * mean + 1e-5f) * gm.y; b.y = bt.y - mean * a.y;
        mean = sm.z * inv; a.z = rsqrtf(sq.z * inv - mean * mean + 1e-5f) * gm.z; b.z = bt.z - mean * a.z;
        mean = sm.w * inv; a.w = rsqrtf(sq.w * inv - mean * mean + 1e-5f) * gm.w; b.w = bt.w - mean * a.w;
    }
    float4 y = ((const float4*)(g_y + (size_t)r * CH))[tid];
    float4 s;
    s.x = fmaxf(fmaf(y.x, a.x, b.x), 0.f);
    s.y = fmaxf(fmaf(y.y, a.y, b.y), 0.f);
    s.z = fmaxf(fmaf(y.z, a.z, b.z), 0.f);
    s.w = fmaxf(fmaf(y.w, a.w, b.w), 0.f);
    float4 m = make_float4(-1e30f, -1e30f, -1e30f, -1e30f);
#pragma unroll
    for (int k = 0; k < KNN; k++) {
        float4 v = ((const float4*)(g_y + (size_t)nb[k] * CH))[tid];
        m.x = fmaxf(m.x, fmaxf(fmaf(v.x, a.x, b.x), 0.f) - s.x);
        m.y = fmaxf(m.y, fmaxf(fmaf(v.y, a.y, b.y), 0.f) - s.y);
        m.z = fmaxf(m.z, fmaxf(fmaf(v.z, a.z, b.z), 0.f) - s.z);
        m.w = fmaxf(m.w, fmaxf(fmaf(v.w, a.w, b.w), 0.f) - s.w);
    }
    float slx, mlx, sly, mly, slz, mlz, slw, mlw;
    uint4 hi, lo;
    hi.x = pack_pair(s.x, m.x, slx, mlx);
    hi.y = pack_pair(s.y, m.y, sly, mly);
    hi.z = pack_pair(s.z, m.z, slz, mlz);
    hi.w = pack_pair(s.w, m.w, slw, mlw);
    lo.x = pack_lo(slx, mlx); lo.y = pack_lo(sly, mly);
    lo.z = pack_lo(slz, mlz); lo.w = pack_lo(slw, mlw);
    ((uint4*)(g_Ahi + (size_t)r * KDIM))[tid] = hi;
    ((uint4*)(g_Alo + (size_t)r * KDIM))[tid] = lo;
}

// ---------------- all weight conversions (fp16 hi only) + stats zero -------------
#define W_ELEMS (CH * KDIM)
#define C_ELEMS ((CH / 2) * CH)
__global__ void wsplit_all(const float* __restrict__ w1, const float* __restrict__ w2,
                           const float* __restrict__ w3, const float* __restrict__ wc1) {
    int i = blockIdx.x * blockDim.x + threadIdx.x;
    if (i < 3 * CH) { g_sum[i] = 0.f; g_sumsq[i] = 0.f; }
    const float* src; __half* hi; int k;
    if (i < W_ELEMS)            { src = w1;  hi = g_Whi;               k = i; }
    else if (i < 2 * W_ELEMS)   { src = w2;  hi = g_Whi + W_ELEMS;     k = i - W_ELEMS; }
    else if (i < 3 * W_ELEMS)   { src = w3;  hi = g_Whi + 2 * W_ELEMS; k = i - 2 * W_ELEMS; }
    else if (i < 3 * W_ELEMS + C_ELEMS) { src = wc1; hi = g_Chi;       k = i - 3 * W_ELEMS; }
    else return;
    hi[k] = __float2half_rn(src[k]);
}

// ============ HMMA fp16 fused-term GEMM (mr layers), 128x128, 2-stage, 2 CTA/SM ==
// C = (Ahi + Alo)*Bh^T + bias; fused column stats into per-layer arrays.
#define MR_STG (3 * 16384)

__global__ void __launch_bounds__(256, 2) mma_gemm(
    const __half* __restrict__ Ahi, const __half* __restrict__ Alo,
    const __half* __restrict__ Bh, const float* __restrict__ bias,
    float* __restrict__ C, float* __restrict__ gsum, float* __restrict__ gsumsq) {
    const int Kd = KDIM, Nn = CH;
    extern __shared__ char smem[];
    uint32_t sb = smem_u32(smem);
    int tid = threadIdx.x, lane = tid & 31, wid = tid >> 5;
    int wm = wid & 1, wn = wid >> 1;
    int row0 = blockIdx.y * 128, col0 = blockIdx.x * 128;
    const int NIT = Kd >> 6;

    float acc[4][4][4];
#pragma unroll
    for (int mi = 0; mi < 4; mi++)
#pragma unroll
        for (int ni = 0; ni < 4; ni++)
#pragma unroll
            for (int j = 0; j < 4; j++) acc[mi][ni][j] = 0.f;

    int lr = tid >> 3, lg = tid & 7;

    auto load_chunk = [&](int kc, int st) {
        uint32_t abase = sb + st * MR_STG;
        uint32_t lbase = abase + 16384;
        uint32_t bbase = abase + 32768;
#pragma unroll
        for (int i = 0; i < 4; i++) {
            int r = lr + i * 32;
            CP_ASYNC16(abase + SWZ((uint32_t)(r * 128 + lg * 16)),
                       Ahi + (size_t)(row0 + r) * Kd + kc * 64 + lg * 8);
        }
#pragma unroll
        for (int i = 0; i < 4; i++) {
            int r = lr + i * 32;
            CP_ASYNC16(lbase + SWZ((uint32_t)(r * 128 + lg * 16)),
                       Alo + (size_t)(row0 + r) * Kd + kc * 64 + lg * 8);
        }
#pragma unroll
        for (int i = 0; i < 4; i++) {
            int r = lr + i * 32;
            CP_ASYNC16(bbase + SWZ((uint32_t)(r * 128 + lg * 16)),
                       Bh + (size_t)(col0 + r) * Kd + kc * 64 + lg * 8);
        }
        CP_COMMIT();
    };

    load_chunk(0, 0);
    load_chunk(1, 1);

    for (int it = 0; it < NIT; it++) {
        int s = it & 1;
        if (it + 1 < NIT) { CP_WAIT1(); } else { CP_WAIT0(); }
        __syncthreads();

        uint32_t abase = sb + s * MR_STG;
        uint32_t bbase = abase + 32768;
#pragma unroll
        for (int kk = 0; kk < 4; kk++) {
            uint32_t bfr[4][2];
#pragma unroll
            for (int ni = 0; ni < 4; ni++) {
                int r = wn * 32 + ni * 8 + (lane & 7);
                uint32_t off = (uint32_t)(r * 128 + kk * 32 + ((lane >> 3) & 1) * 16);
                ldsm_x2(bfr[ni], bbase + SWZ(off));
            }
#pragma unroll
            for (int t = 0; t < 2; t++) {
                uint32_t tbase = abase + t * 16384;
                uint32_t af[4][4];
#pragma unroll
                for (int mi = 0; mi < 4; mi++) {
                    int r = wm * 64 + mi * 16 + (lane & 15);
                    uint32_t off = (uint32_t)(r * 128 + kk * 32 + (lane >> 4) * 16);
                    ldsm_x4(af[mi], tbase + SWZ(off));
                }
#pragma unroll
                for (int ni = 0; ni < 4; ni++)
#pragma unroll
                    for (int mi = 0; mi < 4; mi++)
                        mma16816(acc[mi][ni], af[mi], bfr[ni][0], bfr[ni][1]);
            }
        }
        __syncthreads();
        if (it + 2 < NIT) load_chunk(it + 2, s);
    }

    // epilogue: +bias, store, fused column stats
    float s_[4][2], q_[4][2];
#pragma unroll
    for (int ni = 0; ni < 4; ni++) { s_[ni][0] = s_[ni][1] = q_[ni][0] = q_[ni][1] = 0.f; }
#pragma unroll
    for (int mi = 0; mi < 4; mi++) {
        int row = row0 + wm * 64 + mi * 16 + (lane >> 2);
#pragma unroll
        for (int ni = 0; ni < 4; ni++) {
            int col = col0 + wn * 32 + ni * 8 + (lane & 3) * 2;
            float b0 = bias[col], b1 = bias[col + 1];
            float v0 = acc[mi][ni][0] + b0, v1 = acc[mi][ni][1] + b1;
            float v2 = acc[mi][ni][2] + b0, v3 = acc[mi][ni][3] + b1;
            s_[ni][0] += v0 + v2; s_[ni][1] += v1 + v3;
            q_[ni][0] += v0 * v0 + v2 * v2; q_[ni][1] += v1 * v1 + v3 * v3;
            *(float2*)(C + (size_t)row * Nn + col) = make_float2(v0, v1);
            *(float2*)(C + (size_t)(row + 8) * Nn + col) = make_float2(v2, v3);
        }
    }
#pragma unroll
    for (int ni = 0; ni < 4; ni++) {
#pragma unroll
        for (int j = 0; j < 2; j++) {
#pragma unroll
            for (int off = 4; off <= 16; off <<= 1) {
                s_[ni][j] += __shfl_xor_sync(0xffffffffu, s_[ni][j], off);
                q_[ni][j] += __shfl_xor_sync(0xffffffffu, q_[ni][j], off);
            }
        }
    }
    if ((lane >> 2) == 0) {
#pragma unroll
        for (int ni = 0; ni < 4; ni++) {
            int col = col0 + wn * 32 + ni * 8 + (lane & 3) * 2;
            atomicAdd(&gsum[col],     s_[ni][0]);
            atomicAdd(&gsum[col + 1], s_[ni][1]);
            atomicAdd(&gsumsq[col],     q_[ni][0]);
            atomicAdd(&gsumsq[col + 1], q_[ni][1]);
        }
    }
}

// ===== classifier GEMM with fused BN on A: h = relu(bn(y) @ Chi^T + bc1) =========
// A loaded from fp32 g_y via LDG, bn+relu+fp16 convert, STS. B via cp.async.
// smem: coefA[512]f32 | coefB[512]f32 | A[2][16K] | B[2][16K] = 69632 B.
#define CLS_SMEM (4096 + 4 * 16384)

__global__ void __launch_bounds__(256, 2) cls_gemm(
    const float* __restrict__ y, const __half* __restrict__ Bh,
    const float* __restrict__ gamma, const float* __restrict__ beta,
    const float* __restrict__ gsum, const float* __restrict__ gsumsq,
    const float* __restrict__ bias, float* __restrict__ H) {
    const int Kd = CH, Nn = CH / 2;
    extern __shared__ char smem[];
    float* cA = (float*)smem;          // [512]
    float* cB = (float*)smem + CH;     // [512]
    uint32_t sb = smem_u32(smem) + 4096;
    int tid = threadIdx.x, lane = tid & 31, wid = tid >> 5;
    int wm = wid & 1, wn = wid >> 1;
    int row0 = blockIdx.y * 128, col0 = blockIdx.x * 128;
    const int NIT = Kd >> 6;   // 8

    // BN coefficients for all 512 channels
    {
        const float inv = 1.0f / (float)MROWS;
        for (int c = tid; c < CH; c += 256) {
            float mean = gsum[c] * inv;
            float var  = gsumsq[c] * inv - mean * mean;
            float a = rsqrtf(var + 1e-5f) * gamma[c];
            cA[c] = a;
            cB[c] = beta[c] - mean * a;
        }
    }

    float acc[4][4][4];
#pragma unroll
    for (int mi = 0; mi < 4; mi++)
#pragma unroll
        for (int ni = 0; ni < 4; ni++)
#pragma unroll
            for (int j = 0; j < 4; j++) acc[mi][ni][j] = 0.f;

    int lr = tid >> 3, lg = tid & 7;

    // A loader: fp32 y -> bn+relu -> fp16 -> swizzled smem (stage st)
    auto load_A = [&](int kc, int st) {
        uint32_t abase = sb + st * 16384;
#pragma unroll
        for (int i = 0; i < 4; i++) {
            int e = tid + i * 256;
            int r = e >> 3, g = e & 7;
            const float* yp = y + (size_t)(row0 + r) * Kd + kc * 64 + g * 8;
            float4 v0 = *(const float4*)yp;
            float4 v1 = *(const float4*)(yp + 4);
            int c0 = kc * 64 + g * 8;
            __half hh[8];
            hh[0] = __float2half_rn(fmaxf(fmaf(v0.x, cA[c0 + 0], cB[c0 + 0]), 0.f));
            hh[1] = __float2half_rn(fmaxf(fmaf(v0.y, cA[c0 + 1], cB[c0 + 1]), 0.f));
            hh[2] = __float2half_rn(fmaxf(fmaf(v0.z, cA[c0 + 2], cB[c0 + 2]), 0.f));
            hh[3] = __float2half_rn(fmaxf(fmaf(v0.w, cA[c0 + 3], cB[c0 + 3]), 0.f));
            hh[4] = __float2half_rn(fmaxf(fmaf(v1.x, cA[c0 + 4], cB[c0 + 4]), 0.f));
            hh[5] = __float2half_rn(fmaxf(fmaf(v1.y, cA[c0 + 5], cB[c0 + 5]), 0.f));
            hh[6] = __float2half_rn(fmaxf(fmaf(v1.z, cA[c0 + 6], cB[c0 + 6]), 0.f));
            hh[7] = __float2half_rn(fmaxf(fmaf(v1.w, cA[c0 + 7], cB[c0 + 7]), 0.f));
            *(uint4*)(smem + 4096 + st * 16384 + SWZ((uint32_t)(r * 128 + g * 16))) = *(uint4*)hh;
        }
    };
    auto load_B = [&](int kc, int st) {
        uint32_t bbase = sb + 32768 + st * 16384;
#pragma unroll
        for (int i = 0; i < 4; i++) {
            int r = lr + i * 32;
            CP_ASYNC16(bbase + SWZ((uint32_t)(r * 128 + lg * 16)),
                       Bh + (size_t)(col0 + r) * Kd + kc * 64 + lg * 8);
        }
        CP_COMMIT();
    };

    load_B(0, 0);
    load_B(1, 1);
    __syncthreads();   // coef table ready
    load_A(0, 0);

    for (int it = 0; it < NIT; it++) {
        int s = it & 1;
        if (it + 1 < NIT) { CP_WAIT1(); } else { CP_WAIT0(); }
        __syncthreads();
        if (it + 1 < NIT) load_A(it + 1, 1 - s);   // writes other stage

        uint32_t abase = sb + s * 16384;
        uint32_t bbase = sb + 32768 + s * 16384;
#pragma unroll
        for (int kk = 0; kk < 4; kk++) {
            uint32_t bfr[4][2];
#pragma unroll
            for (int ni = 0; ni < 4; ni++) {
                int r = wn * 32 + ni * 8 + (lane & 7);
                uint32_t off = (uint32_t)(r * 128 + kk * 32 + ((lane >> 3) & 1) * 16);
                ldsm_x2(bfr[ni], bbase + SWZ(off));
            }
            uint32_t af[4][4];
#pragma unroll
            for (int mi = 0; mi < 4; mi++) {
                int r = wm * 64 + mi * 16 + (lane & 15);
                uint32_t off = (uint32_t)(r * 128 + kk * 32 + (lane >> 4) * 16);
                ldsm_x4(af[mi], abase + SWZ(off));
            }
#pragma unroll
            for (int ni = 0; ni < 4; ni++)
#pragma unroll
                for (int mi = 0; mi < 4; mi++)
                    mma16816(acc[mi][ni], af[mi], bfr[ni][0], bfr[ni][1]);
        }
        __syncthreads();
        if (it + 2 < NIT) load_B(it + 2, s);
    }

    // epilogue: +bias, relu, store h
#pragma unroll
    for (int mi = 0; mi < 4; mi++) {
        int row = row0 + wm * 64 + mi * 16 + (lane >> 2);
#pragma unroll
        for (int ni = 0; ni < 4; ni++) {
            int col = col0 + wn * 32 + ni * 8 + (lane & 3) * 2;
            float b0 = bias[col], b1 = bias[col + 1];
            float v0 = fmaxf(acc[mi][ni][0] + b0, 0.f), v1 = fmaxf(acc[mi][ni][1] + b1, 0.f);
            float v2 = fmaxf(acc[mi][ni][2] + b0, 0.f), v3 = fmaxf(acc[mi][ni][3] + b1, 0.f);
            *(float2*)(H + (size_t)row * Nn + col) = make_float2(v0, v1);
            *(float2*)(H + (size_t)(row + 8) * Nn + col) = make_float2(v2, v3);
        }
    }
}

// ---------------- final tiny GEMM: out[M,5] = h[M,256] @ Wc2[5,256]^T + bc2 -----
__global__ void final_kernel(const float* __restrict__ Wc2, const float* __restrict__ bc2,
                             float* __restrict__ out) {
    __shared__ float w[5 * 256];
    for (int i = threadIdx.x; i < 5 * 256; i += blockDim.x) w[i] = Wc2[i];
    __syncthreads();
    int warp = threadIdx.x >> 5, lane = threadIdx.x & 31;
    int r = blockIdx.x * (blockDim.x >> 5) + warp;
    const float* h = g_h + (size_t)r * 256;
    float a0 = 0, a1 = 0, a2 = 0, a3 = 0, a4 = 0;
    for (int c = lane; c < 256; c += 32) {
        float hv = h[c];
        a0 = fmaf(hv, w[0 * 256 + c], a0);
        a1 = fmaf(hv, w[1 * 256 + c], a1);
        a2 = fmaf(hv, w[2 * 256 + c], a2);
        a3 = fmaf(hv, w[3 * 256 + c], a3);
        a4 = fmaf(hv, w[4 * 256 + c], a4);
    }
#pragma unroll
    for (int off = 16; off; off >>= 1) {
        a0 += __shfl_xor_sync(0xffffffffu, a0, off);
        a1 += __shfl_xor_sync(0xffffffffu, a1, off);
        a2 += __shfl_xor_sync(0xffffffffu, a2, off);
        a3 += __shfl_xor_sync(0xffffffffu, a3, off);
        a4 += __shfl_xor_sync(0xffffffffu, a4, off);
    }
    if (lane == 0) {
        float* o = out + (size_t)r * 5;
        o[0] = a0 + bc2[0];
        o[1] = a1 + bc2[1];
        o[2] = a2 + bc2[2];
        o[3] = a3 + bc2[3];
        o[4] = a4 + bc2[4];
    }
}

// ---------------- launch ----------------
extern "C" void kernel_launch(void* const* d_in, const int* in_sizes, int n_in,
                              void* d_out, int out_size) {
    const float* x    = (const float*)d_in[0];
    const float* pos  = (const float*)d_in[1];
    const float* W[3]  = {(const float*)d_in[2], (const float*)d_in[6], (const float*)d_in[10]};
    const float* bb[3] = {(const float*)d_in[3], (const float*)d_in[7], (const float*)d_in[11]};
    const float* gg[3] = {(const float*)d_in[4], (const float*)d_in[8], (const float*)d_in[12]};
    const float* be[3] = {(const float*)d_in[5], (const float*)d_in[9], (const float*)d_in[13]};
    const float* Wc1 = (const float*)d_in[14];
    const float* bc1 = (const float*)d_in[15];
    const float* Wc2 = (const float*)d_in[16];
    const float* bc2 = (const float*)d_in[17];
    float* out = (float*)d_out;

    float *p_y, *p_h, *p_sum, *p_sumsq;
    __half *p_Ahi, *p_Alo, *p_Whi, *p_Chi;
    cudaGetSymbolAddress((void**)&p_y, g_y);
    cudaGetSymbolAddress((void**)&p_h, g_h);
    cudaGetSymbolAddress((void**)&p_sum, g_sum);
    cudaGetSymbolAddress((void**)&p_sumsq, g_sumsq);
    cudaGetSymbolAddress((void**)&p_Ahi, g_Ahi);
    cudaGetSymbolAddress((void**)&p_Alo, g_Alo);
    cudaGetSymbolAddress((void**)&p_Whi, g_Whi);
    cudaGetSymbolAddress((void**)&p_Chi, g_Chi);

    cudaFuncSetAttribute(mma_gemm, cudaFuncAttributeMaxDynamicSharedMemorySize, 2 * MR_STG);
    cudaFuncSetAttribute(cls_gemm, cudaFuncAttributeMaxDynamicSharedMemorySize, CLS_SMEM);

    transpose_kernel<<<dim3(NPTS / 32, CH / 32, BATCH), dim3(32, 8)>>>(x);
    knn_kernel<<<dim3(NPTS / 8, BATCH), 256>>>(pos);
    wsplit_all<<<(3 * W_ELEMS + C_ELEMS) / 256, 256>>>(W[0], W[1], W[2], Wc1);

    for (int i = 0; i < 3; i++) {
        if (i == 0) feat_kernel<<<MROWS, 128>>>();
        else        bnfeat_kernel<<<MROWS, 128>>>(gg[i - 1], be[i - 1],
                                                  p_sum + (i - 1) * CH, p_sumsq + (i - 1) * CH);
        mma_gemm<<<dim3(CH / 128, MROWS / 128), 256, 2 * MR_STG>>>(
            p_Ahi, p_Alo, p_Whi + (size_t)i * CH * KDIM, bb[i], p_y,
            p_sum + i * CH, p_sumsq + i * CH);
    }

    // classifier with fused BN(layer-3 stats) on A
    cls_gemm<<<dim3((CH / 2) / 128, MROWS / 128), 256, CLS_SMEM>>>(
        p_y, p_Chi, gg[2], be[2], p_sum + 2 * CH, p_sumsq + 2 * CH, bc1, p_h);
    final_kernel<<<MROWS / 8, 256>>>(Wc2, bc2, out);
}

// round 15
// speedup vs baseline: 1.0189x; 1.0189x over previous
#include <cuda_runtime.h>
#include <cuda_fp16.h>
#include <cstdint>

#define BATCH 4
#define CH    512
#define NPTS  4096
#define MROWS (BATCH * NPTS)   // 16384
#define KNN   5
#define KDIM  (2 * CH)         // 1024

// ================= PTX helpers (baseline ISA only — no sm_103a features) =========
__device__ __forceinline__ uint32_t smem_u32(const void* p) {
    return (uint32_t)__cvta_generic_to_shared((void*)p);
}
#define SWZ(o) ((o) ^ (((o) >> 3) & 0x70))

__device__ __forceinline__ void ldsm_x4(uint32_t (&r)[4], uint32_t addr) {
    asm volatile("ldmatrix.sync.aligned.m8n8.x4.shared.b16 {%0,%1,%2,%3}, [%4];"
                 : "=r"(r[0]), "=r"(r[1]), "=r"(r[2]), "=r"(r[3]) : "r"(addr));
}
__device__ __forceinline__ void ldsm_x2(uint32_t (&r)[2], uint32_t addr) {
    asm volatile("ldmatrix.sync.aligned.m8n8.x2.shared.b16 {%0,%1}, [%2];"
                 : "=r"(r[0]), "=r"(r[1]) : "r"(addr));
}
__device__ __forceinline__ void mma16816(float (&c)[4], const uint32_t (&a)[4],
                                         uint32_t b0, uint32_t b1) {
    asm volatile("mma.sync.aligned.m16n8k16.row.col.f32.f16.f16.f32 "
                 "{%0,%1,%2,%3}, {%4,%5,%6,%7}, {%8,%9}, {%0,%1,%2,%3};"
                 : "+f"(c[0]), "+f"(c[1]), "+f"(c[2]), "+f"(c[3])
                 : "r"(a[0]), "r"(a[1]), "r"(a[2]), "r"(a[3]), "r"(b0), "r"(b1));
}
#define CP_ASYNC16(dst, src) \
    asm volatile("cp.async.cg.shared.global [%0], [%1], 16;" :: "r"(dst), "l"(src))
#define CP_COMMIT() asm volatile("cp.async.commit_group;" ::: "memory")
#define CP_WAIT1()  asm volatile("cp.async.wait_group 1;" ::: "memory")
#define CP_WAIT0()  asm volatile("cp.async.wait_group 0;" ::: "memory")

// ================= scratch (static device globals; no allocation) =================
__device__ float g_xt[(size_t)MROWS * CH];
__device__ __align__(16) __half g_Ahi[(size_t)MROWS * KDIM];
__device__ __align__(16) __half g_Alo[(size_t)MROWS * KDIM];
__device__ __align__(16) __half g_Xhi[(size_t)MROWS * CH];
__device__ __align__(16) __half g_Whi[(size_t)3 * CH * KDIM];
__device__ __align__(16) __half g_Chi[(size_t)(CH / 2) * CH];
__device__ float g_y[(size_t)MROWS * CH];
__device__ float g_h[(size_t)MROWS * (CH / 2)];
__device__ int   g_idx[MROWS * KNN];
__device__ __align__(16) float g_sum[3 * CH];    // per-layer column sums
__device__ __align__(16) float g_sumsq[3 * CH];

__device__ __forceinline__ uint32_t pack_pair(float s, float m, float& sl, float& ml) {
    __half2 v;
    v.x = __float2half_rn(s);
    v.y = __float2half_rn(m);
    sl = s - __half2float(v.x);
    ml = m - __half2float(v.y);
    return *(uint32_t*)&v;
}
__device__ __forceinline__ uint32_t pack_lo(float sl, float ml) {
    __half2 v;
    v.x = __float2half_rn(sl);
    v.y = __float2half_rn(ml);
    return *(uint32_t*)&v;
}

// ---------------- transpose: x [B,C,N] -> g_xt [B*N, C] ----------------
__global__ void transpose_kernel(const float* __restrict__ x) {
    __shared__ float tile[32][33];
    int b = blockIdx.z;
    int n0 = blockIdx.x * 32, c0 = blockIdx.y * 32;
    int tx = threadIdx.x, ty = threadIdx.y;
#pragma unroll
    for (int i = 0; i < 4; i++) {
        int c = c0 + ty + i * 8;
        tile[ty + i * 8][tx] = x[((size_t)(b * CH + c)) * NPTS + n0 + tx];
    }
    __syncthreads();
#pragma unroll
    for (int i = 0; i < 4; i++) {
        int n = n0 + ty + i * 8;
        g_xt[((size_t)(b * NPTS + n)) * CH + c0 + tx] = tile[tx][ty + i * 8];
    }
}

// ---------------- KNN (bit-exact vs reference; DO NOT TOUCH) ----------------
#define LTC(da, ia, db, ib) ((da) < (db) || ((da) == (db) && (ia) < (ib)))

__global__ void knn_kernel(const float* __restrict__ pos) {
    __shared__ float sx[NPTS];
    __shared__ float sy[NPTS];
    __shared__ float sd[NPTS];
    int b = blockIdx.y;
    const float* p = pos + (size_t)b * NPTS * 2;
    for (int j = threadIdx.x; j < NPTS; j += blockDim.x) {
        float xx = p[2 * j], yy = p[2 * j + 1];
        sx[j] = xx; sy[j] = yy;
        sd[j] = __fadd_rn(__fmul_rn(xx, xx), __fmul_rn(yy, yy));  // add-form d2
    }
    __syncthreads();

    int warp = threadIdx.x >> 5, lane = threadIdx.x & 31;
    int q = blockIdx.x * (blockDim.x >> 5) + warp;

    float xi = sx[q], yi = sy[q], d2i = sd[q];
    const float INF = __int_as_float(0x7f800000);
    float d0 = INF, d1 = INF, d2 = INF, d3 = INF, d4 = INF;
    int   i0 = 0x7fffffff, i1 = 0x7fffffff, i2 = 0x7fffffff, i3 = 0x7fffffff, i4 = 0x7fffffff;

    for (int j = lane; j < NPTS; j += 32) {
        float dot  = __fmaf_rn(yi, sy[j], __fmul_rn(xi, sx[j]));  // fma-form dot
        float dist = __fadd_rn(__fadd_rn(d2i, sd[j]), -__fmul_rn(2.0f, dot));
        if (LTC(dist, j, d4, i4)) {
            d4 = dist; i4 = j;
            if (LTC(d4, i4, d3, i3)) { float tf = d3; d3 = d4; d4 = tf; int ti = i3; i3 = i4; i4 = ti; }
            if (LTC(d3, i3, d2, i2)) { float tf = d2; d2 = d3; d3 = tf; int ti = i2; i2 = i3; i3 = ti; }
            if (LTC(d2, i2, d1, i1)) { float tf = d1; d1 = d2; d2 = tf; int ti = i1; i1 = i2; i2 = ti; }
            if (LTC(d1, i1, d0, i0)) { float tf = d0; d0 = d1; d1 = tf; int ti = i0; i0 = i1; i1 = ti; }
        }
    }
#pragma unroll
    for (int k = 0; k < KNN; k++) {
        float od = d0; int oi = i0;
#pragma unroll
        for (int off = 16; off; off >>= 1) {
            float td = __shfl_down_sync(0xffffffffu, od, off);
            int   ti = __shfl_down_sync(0xffffffffu, oi, off);
            if (LTC(td, ti, od, oi)) { od = td; oi = ti; }
        }
        od = __shfl_sync(0xffffffffu, od, 0);
        oi = __shfl_sync(0xffffffffu, oi, 0);
        if (oi == i0) {
            d0 = d1; i0 = i1; d1 = d2; i1 = i2; d2 = d3; i2 = i3; d3 = d4; i3 = i4;
            d4 = INF; i4 = 0x7fffffff;
        }
        if (lane == 0) g_idx[((size_t)(b * NPTS + q)) * KNN + k] = oi;
    }
}

// ---------------- feat (layer 1): 1 row per 128-thread block, float4 -------------
__global__ void feat_kernel() {
    __shared__ int nb[KNN];
    int r = blockIdx.x, tid = threadIdx.x;
    if (tid < KNN) nb[tid] = (r >> 12) * NPTS + g_idx[r * KNN + tid];
    __syncthreads();
    float4 s = ((const float4*)(g_xt + (size_t)r * CH))[tid];
    float4 m = make_float4(-1e30f, -1e30f, -1e30f, -1e30f);
#pragma unroll
    for (int k = 0; k < KNN; k++) {
        float4 v = ((const float4*)(g_xt + (size_t)nb[k] * CH))[tid];
        m.x = fmaxf(m.x, v.x - s.x); m.y = fmaxf(m.y, v.y - s.y);
        m.z = fmaxf(m.z, v.z - s.z); m.w = fmaxf(m.w, v.w - s.w);
    }
    float slx, mlx, sly, mly, slz, mlz, slw, mlw;
    uint4 hi, lo;
    hi.x = pack_pair(s.x, m.x, slx, mlx);
    hi.y = pack_pair(s.y, m.y, sly, mly);
    hi.z = pack_pair(s.z, m.z, slz, mlz);
    hi.w = pack_pair(s.w, m.w, slw, mlw);
    lo.x = pack_lo(slx, mlx); lo.y = pack_lo(sly, mly);
    lo.z = pack_lo(slz, mlz); lo.w = pack_lo(slw, mlw);
    ((uint4*)(g_Ahi + (size_t)r * KDIM))[tid] = hi;
    ((uint4*)(g_Alo + (size_t)r * KDIM))[tid] = lo;
}

// ---- bnfeat (layers 2,3): inline BN coefs from per-layer stats, gather+maxrel ----
__global__ void bnfeat_kernel(const float* __restrict__ gamma, const float* __restrict__ beta,
                              const float* __restrict__ gsum, const float* __restrict__ gsumsq) {
    __shared__ int nb[KNN];
    int r = blockIdx.x, tid = threadIdx.x;
    if (tid < KNN) nb[tid] = (r >> 12) * NPTS + g_idx[r * KNN + tid];
    __syncthreads();
    const float inv = 1.0f / (float)MROWS;
    float4 sm = ((const float4*)gsum)[tid];
    float4 sq = ((const float4*)gsumsq)[tid];
    float4 gm = ((const float4*)gamma)[tid];
    float4 bt = ((const float4*)beta)[tid];
    float4 a, b;
    {
        float mean;
        mean = sm.x * inv; a.x = rsqrtf(sq.x * inv - mean * mean + 1e-5f) * gm.x; b.x = bt.x - mean * a.x;
        mean = sm.y * inv; a.y = rsqrtf(sq.y * inv - mean * mean + 1e-5f) * gm.y; b.y = bt.y - mean * a.y;
        mean = sm.z * inv; a.z = rsqrtf(sq.z * inv - mean * mean + 1e-5f) * gm.z; b.z = bt.z - mean * a.z;
        mean = sm.w * inv; a.w = rsqrtf(sq.w * inv - mean * mean + 1e-5f) * gm.w; b.w = bt.w - mean * a.w;
    }
    float4 y = ((const float4*)(g_y + (size_t)r * CH))[tid];
    float4 s;
    s.x = fmaxf(fmaf(y.x, a.x, b.x), 0.f);
    s.y = fmaxf(fmaf(y.y, a.y, b.y), 0.f);
    s.z = fmaxf(fmaf(y.z, a.z, b.z), 0.f);
    s.w = fmaxf(fmaf(y.w, a.w, b.w), 0.f);
    float4 m = make_float4(-1e30f, -1e30f, -1e30f, -1e30f);
#pragma unroll
    for (int k = 0; k < KNN; k++) {
        float4 v = ((const float4*)(g_y + (size_t)nb[k] * CH))[tid];
        m.x = fmaxf(m.x, fmaxf(fmaf(v.x, a.x, b.x), 0.f) - s.x);
        m.y = fmaxf(m.y, fmaxf(fmaf(v.y, a.y, b.y), 0.f) - s.y);
        m.z = fmaxf(m.z, fmaxf(fmaf(v.z, a.z, b.z), 0.f) - s.z);
        m.w = fmaxf(m.w, fmaxf(fmaf(v.w, a.w, b.w), 0.f) - s.w);
    }
    float slx, mlx, sly, mly, slz, mlz, slw, mlw;
    uint4 hi, lo;
    hi.x = pack_pair(s.x, m.x, slx, mlx);
    hi.y = pack_pair(s.y, m.y, sly, mly);
    hi.z = pack_pair(s.z, m.z, slz, mlz);
    hi.w = pack_pair(s.w, m.w, slw, mlw);
    lo.x = pack_lo(slx, mlx); lo.y = pack_lo(sly, mly);
    lo.z = pack_lo(slz, mlz); lo.w = pack_lo(slw, mlw);
    ((uint4*)(g_Ahi + (size_t)r * KDIM))[tid] = hi;
    ((uint4*)(g_Alo + (size_t)r * KDIM))[tid] = lo;
}

// ---- bn_apply_cls: inline coefs from layer-3 stats, g_y -> Xhi (fp16), float4 ---
__global__ void bn_apply_cls(const float* __restrict__ gamma, const float* __restrict__ beta,
                             const float* __restrict__ gsum, const float* __restrict__ gsumsq) {
    int i4 = blockIdx.x * blockDim.x + threadIdx.x;   // float4 index
    int c4 = i4 & 127;
    const float inv = 1.0f / (float)MROWS;
    float4 sm = ((const float4*)gsum)[c4];
    float4 sq = ((const float4*)gsumsq)[c4];
    float4 gm = ((const float4*)gamma)[c4];
    float4 bt = ((const float4*)beta)[c4];
    float4 a, b;
    {
        float mean;
        mean = sm.x * inv; a.x = rsqrtf(sq.x * inv - mean * mean + 1e-5f) * gm.x; b.x = bt.x - mean * a.x;
        mean = sm.y * inv; a.y = rsqrtf(sq.y * inv - mean * mean + 1e-5f) * gm.y; b.y = bt.y - mean * a.y;
        mean = sm.z * inv; a.z = rsqrtf(sq.z * inv - mean * mean + 1e-5f) * gm.z; b.z = bt.z - mean * a.z;
        mean = sm.w * inv; a.w = rsqrtf(sq.w * inv - mean * mean + 1e-5f) * gm.w; b.w = bt.w - mean * a.w;
    }
    float4 y = ((const float4*)g_y)[i4];
    float vx = fmaxf(fmaf(y.x, a.x, b.x), 0.f);
    float vy = fmaxf(fmaf(y.y, a.y, b.y), 0.f);
    float vz = fmaxf(fmaf(y.z, a.z, b.z), 0.f);
    float vw = fmaxf(fmaf(y.w, a.w, b.w), 0.f);
    __half2 h0; h0.x = __float2half_rn(vx); h0.y = __float2half_rn(vy);
    __half2 h1; h1.x = __float2half_rn(vz); h1.y = __float2half_rn(vw);
    uint2 hv = make_uint2(*(uint32_t*)&h0, *(uint32_t*)&h1);
    ((uint2*)g_Xhi)[i4] = hv;
}

// ---------------- all weight conversions (fp16 hi only) + stats zero -------------
#define W_ELEMS (CH * KDIM)
#define C_ELEMS ((CH / 2) * CH)
__global__ void wsplit_all(const float* __restrict__ w1, const float* __restrict__ w2,
                           const float* __restrict__ w3, const float* __restrict__ wc1) {
    int i = blockIdx.x * blockDim.x + threadIdx.x;
    if (i < 3 * CH) { g_sum[i] = 0.f; g_sumsq[i] = 0.f; }
    const float* src; __half* hi; int k;
    if (i < W_ELEMS)            { src = w1;  hi = g_Whi;               k = i; }
    else if (i < 2 * W_ELEMS)   { src = w2;  hi = g_Whi + W_ELEMS;     k = i - W_ELEMS; }
    else if (i < 3 * W_ELEMS)   { src = w3;  hi = g_Whi + 2 * W_ELEMS; k = i - 2 * W_ELEMS; }
    else if (i < 3 * W_ELEMS + C_ELEMS) { src = wc1; hi = g_Chi;       k = i - 3 * W_ELEMS; }
    else return;
    hi[k] = __float2half_rn(src[k]);
}

// ============ HMMA fp16 fused-term GEMM, 128x128 tile, 2-stage, 2 CTA/SM =========
// TERMS=2: C = (Ahi + Alo)*Bh^T + bias, both terms per K-chunk (B tile shared).
// TERMS=1: C = Ahi*Bh^T + bias.
// 8 warps (2M x 4N), warp 64x32. K chunks of 64 fp16.
// Stage = [Ahi 16K | (Alo 16K) | B 16K] = (TERMS+1)*16 KB; 2 stages.

template <int RELU, int STATS, int TERMS>
__global__ void __launch_bounds__(256, 2) mma_gemm(
    const __half* __restrict__ Ahi, const __half* __restrict__ Alo,
    const __half* __restrict__ Bh,
    const float* __restrict__ bias, float* __restrict__ C,
    float* __restrict__ gsum, float* __restrict__ gsumsq, int Kd, int Nn) {
    constexpr int STG = (TERMS + 1) * 16384;
    extern __shared__ char smem[];
    uint32_t sb = smem_u32(smem);
    int tid = threadIdx.x, lane = tid & 31, wid = tid >> 5;
    int wm = wid & 1, wn = wid >> 1;
    int row0 = blockIdx.y * 128, col0 = blockIdx.x * 128;
    int NIT = Kd >> 6;

    float acc[4][4][4];
#pragma unroll
    for (int mi = 0; mi < 4; mi++)
#pragma unroll
        for (int ni = 0; ni < 4; ni++)
#pragma unroll
            for (int j = 0; j < 4; j++) acc[mi][ni][j] = 0.f;

    int lr = tid >> 3, lg = tid & 7;

    auto load_chunk = [&](int kc, int st) {
        uint32_t abase = sb + st * STG;
        uint32_t bbase = abase + TERMS * 16384;
#pragma unroll
        for (int i = 0; i < 4; i++) {
            int r = lr + i * 32;
            CP_ASYNC16(abase + SWZ((uint32_t)(r * 128 + lg * 16)),
                       Ahi + (size_t)(row0 + r) * Kd + kc * 64 + lg * 8);
        }
        if (TERMS == 2) {
            uint32_t lbase = abase + 16384;
#pragma unroll
            for (int i = 0; i < 4; i++) {
                int r = lr + i * 32;
                CP_ASYNC16(lbase + SWZ((uint32_t)(r * 128 + lg * 16)),
                           Alo + (size_t)(row0 + r) * Kd + kc * 64 + lg * 8);
            }
        }
#pragma unroll
        for (int i = 0; i < 4; i++) {
            int r = lr + i * 32;
            CP_ASYNC16(bbase + SWZ((uint32_t)(r * 128 + lg * 16)),
                       Bh + (size_t)(col0 + r) * Kd + kc * 64 + lg * 8);
        }
        CP_COMMIT();
    };

    load_chunk(0, 0);
    load_chunk(1, 1);

    for (int it = 0; it < NIT; it++) {
        int s = it & 1;
        if (it + 1 < NIT) { CP_WAIT1(); } else { CP_WAIT0(); }
        __syncthreads();

        uint32_t abase = sb + s * STG;
        uint32_t bbase = abase + TERMS * 16384;
#pragma unroll
        for (int kk = 0; kk < 4; kk++) {
            uint32_t bfr[4][2];
#pragma unroll
            for (int ni = 0; ni < 4; ni++) {
                int r = wn * 32 + ni * 8 + (lane & 7);
                uint32_t off = (uint32_t)(r * 128 + kk * 32 + ((lane >> 3) & 1) * 16);
                ldsm_x2(bfr[ni], bbase + SWZ(off));
            }
#pragma unroll
            for (int t = 0; t < TERMS; t++) {
                uint32_t tbase = abase + t * 16384;
                uint32_t af[4][4];
#pragma unroll
                for (int mi = 0; mi < 4; mi++) {
                    int r = wm * 64 + mi * 16 + (lane & 15);
                    uint32_t off = (uint32_t)(r * 128 + kk * 32 + (lane >> 4) * 16);
                    ldsm_x4(af[mi], tbase + SWZ(off));
                }
#pragma unroll
                for (int ni = 0; ni < 4; ni++)
#pragma unroll
                    for (int mi = 0; mi < 4; mi++)
                        mma16816(acc[mi][ni], af[mi], bfr[ni][0], bfr[ni][1]);
            }
        }
        __syncthreads();
        if (it + 2 < NIT) load_chunk(it + 2, s);
    }

    // epilogue: +bias, optional relu, store; optional fused column stats
    float s_[4][2], q_[4][2];
    if (STATS) {
#pragma unroll
        for (int ni = 0; ni < 4; ni++) { s_[ni][0] = s_[ni][1] = q_[ni][0] = q_[ni][1] = 0.f; }
    }
#pragma unroll
    for (int mi = 0; mi < 4; mi++) {
        int row = row0 + wm * 64 + mi * 16 + (lane >> 2);
#pragma unroll
        for (int ni = 0; ni < 4; ni++) {
            int col = col0 + wn * 32 + ni * 8 + (lane & 3) * 2;
            float b0 = bias[col], b1 = bias[col + 1];
            float v0 = acc[mi][ni][0] + b0, v1 = acc[mi][ni][1] + b1;
            float v2 = acc[mi][ni][2] + b0, v3 = acc[mi][ni][3] + b1;
            if (RELU) {
                v0 = fmaxf(v0, 0.f); v1 = fmaxf(v1, 0.f);
                v2 = fmaxf(v2, 0.f); v3 = fmaxf(v3, 0.f);
            }
            if (STATS) {
                s_[ni][0] += v0 + v2; s_[ni][1] += v1 + v3;
                q_[ni][0] += v0 * v0 + v2 * v2; q_[ni][1] += v1 * v1 + v3 * v3;
            }
            *(float2*)(C + (size_t)row * Nn + col) = make_float2(v0, v1);
            *(float2*)(C + (size_t)(row + 8) * Nn + col) = make_float2(v2, v3);
        }
    }
    if (STATS) {
#pragma unroll
        for (int ni = 0; ni < 4; ni++) {
#pragma unroll
            for (int j = 0; j < 2; j++) {
#pragma unroll
                for (int off = 4; off <= 16; off <<= 1) {
                    s_[ni][j] += __shfl_xor_sync(0xffffffffu, s_[ni][j], off);
                    q_[ni][j] += __shfl_xor_sync(0xffffffffu, q_[ni][j], off);
                }
            }
        }
        if ((lane >> 2) == 0) {
#pragma unroll
            for (int ni = 0; ni < 4; ni++) {
                int col = col0 + wn * 32 + ni * 8 + (lane & 3) * 2;
                atomicAdd(&gsum[col],     s_[ni][0]);
                atomicAdd(&gsum[col + 1], s_[ni][1]);
                atomicAdd(&gsumsq[col],     q_[ni][0]);
                atomicAdd(&gsumsq[col + 1], q_[ni][1]);
            }
        }
    }
}

// ---------------- final tiny GEMM: out[M,5] = h[M,256] @ Wc2[5,256]^T + bc2 -----
__global__ void final_kernel(const float* __restrict__ Wc2, const float* __restrict__ bc2,
                             float* __restrict__ out) {
    __shared__ float w[5 * 256];
    for (int i = threadIdx.x; i < 5 * 256; i += blockDim.x) w[i] = Wc2[i];
    __syncthreads();
    int warp = threadIdx.x >> 5, lane = threadIdx.x & 31;
    int r = blockIdx.x * (blockDim.x >> 5) + warp;
    const float* h = g_h + (size_t)r * 256;
    float a0 = 0, a1 = 0, a2 = 0, a3 = 0, a4 = 0;
    for (int c = lane; c < 256; c += 32) {
        float hv = h[c];
        a0 = fmaf(hv, w[0 * 256 + c], a0);
        a1 = fmaf(hv, w[1 * 256 + c], a1);
        a2 = fmaf(hv, w[2 * 256 + c], a2);
        a3 = fmaf(hv, w[3 * 256 + c], a3);
        a4 = fmaf(hv, w[4 * 256 + c], a4);
    }
#pragma unroll
    for (int off = 16; off; off >>= 1) {
        a0 += __shfl_xor_sync(0xffffffffu, a0, off);
        a1 += __shfl_xor_sync(0xffffffffu, a1, off);
        a2 += __shfl_xor_sync(0xffffffffu, a2, off);
        a3 += __shfl_xor_sync(0xffffffffu, a3, off);
        a4 += __shfl_xor_sync(0xffffffffu, a4, off);
    }
    if (lane == 0) {
        float* o = out + (size_t)r * 5;
        o[0] = a0 + bc2[0];
        o[1] = a1 + bc2[1];
        o[2] = a2 + bc2[2];
        o[3] = a3 + bc2[3];
        o[4] = a4 + bc2[4];
    }
}

// ---------------- launch ----------------
extern "C" void kernel_launch(void* const* d_in, const int* in_sizes, int n_in,
                              void* d_out, int out_size) {
    const float* x    = (const float*)d_in[0];
    const float* pos  = (const float*)d_in[1];
    const float* W[3]  = {(const float*)d_in[2], (const float*)d_in[6], (const float*)d_in[10]};
    const float* bb[3] = {(const float*)d_in[3], (const float*)d_in[7], (const float*)d_in[11]};
    const float* gg[3] = {(const float*)d_in[4], (const float*)d_in[8], (const float*)d_in[12]};
    const float* be[3] = {(const float*)d_in[5], (const float*)d_in[9], (const float*)d_in[13]};
    const float* Wc1 = (const float*)d_in[14];
    const float* bc1 = (const float*)d_in[15];
    const float* Wc2 = (const float*)d_in[16];
    const float* bc2 = (const float*)d_in[17];
    float* out = (float*)d_out;

    float *p_y, *p_h, *p_sum, *p_sumsq;
    __half *p_Ahi, *p_Alo, *p_Xhi, *p_Whi, *p_Chi;
    cudaGetSymbolAddress((void**)&p_y, g_y);
    cudaGetSymbolAddress((void**)&p_h, g_h);
    cudaGetSymbolAddress((void**)&p_sum, g_sum);
    cudaGetSymbolAddress((void**)&p_sumsq, g_sumsq);
    cudaGetSymbolAddress((void**)&p_Ahi, g_Ahi);
    cudaGetSymbolAddress((void**)&p_Alo, g_Alo);
    cudaGetSymbolAddress((void**)&p_Xhi, g_Xhi);
    cudaGetSymbolAddress((void**)&p_Whi, g_Whi);
    cudaGetSymbolAddress((void**)&p_Chi, g_Chi);

    cudaFuncSetAttribute(mma_gemm<0, 1, 2>, cudaFuncAttributeMaxDynamicSharedMemorySize, 2 * 3 * 16384);
    cudaFuncSetAttribute(mma_gemm<1, 0, 1>, cudaFuncAttributeMaxDynamicSharedMemorySize, 2 * 2 * 16384);

    transpose_kernel<<<dim3(NPTS / 32, CH / 32, BATCH), dim3(32, 8)>>>(x);
    knn_kernel<<<dim3(NPTS / 8, BATCH), 256>>>(pos);
    wsplit_all<<<(3 * W_ELEMS + C_ELEMS) / 256, 256>>>(W[0], W[1], W[2], Wc1);

    for (int i = 0; i < 3; i++) {
        if (i == 0) feat_kernel<<<MROWS, 128>>>();
        else        bnfeat_kernel<<<MROWS, 128>>>(gg[i - 1], be[i - 1],
                                                  p_sum + (i - 1) * CH, p_sumsq + (i - 1) * CH);
        mma_gemm<0, 1, 2><<<dim3(CH / 128, MROWS / 128), 256, 2 * 3 * 16384>>>(
            p_Ahi, p_Alo, p_Whi + (size_t)i * CH * KDIM,
            bb[i], p_y, p_sum + i * CH, p_sumsq + i * CH, KDIM, CH);
    }

    // classifier: Xhi = bn+relu(layer3), then h = relu(X @ Wc1^T + bc1) (1-term)
    bn_apply_cls<<<(MROWS * CH / 4) / 256, 256>>>(gg[2], be[2], p_sum + 2 * CH, p_sumsq + 2 * CH);
    mma_gemm<1, 0, 1><<<dim3((CH / 2) / 128, MROWS / 128), 256, 2 * 2 * 16384>>>(
        p_Xhi, p_Xhi, p_Chi, bc1, p_h, nullptr, nullptr, CH, CH / 2);
    final_kernel<<<MROWS / 8, 256>>>(Wc2, bc2, out);
}

// round 16
// speedup vs baseline: 1.0244x; 1.0054x over previous
#include <cuda_runtime.h>
#include <cuda_fp16.h>
#include <cstdint>

#define BATCH 4
#define CH    512
#define NPTS  4096
#define MROWS (BATCH * NPTS)   // 16384
#define KNN   5
#define KDIM  (2 * CH)         // 1024

// ================= PTX helpers (baseline ISA only — no sm_103a features) =========
__device__ __forceinline__ uint32_t smem_u32(const void* p) {
    return (uint32_t)__cvta_generic_to_shared((void*)p);
}
#define SWZ(o) ((o) ^ (((o) >> 3) & 0x70))

__device__ __forceinline__ void ldsm_x4(uint32_t (&r)[4], uint32_t addr) {
    asm volatile("ldmatrix.sync.aligned.m8n8.x4.shared.b16 {%0,%1,%2,%3}, [%4];"
                 : "=r"(r[0]), "=r"(r[1]), "=r"(r[2]), "=r"(r[3]) : "r"(addr));
}
__device__ __forceinline__ void ldsm_x2(uint32_t (&r)[2], uint32_t addr) {
    asm volatile("ldmatrix.sync.aligned.m8n8.x2.shared.b16 {%0,%1}, [%2];"
                 : "=r"(r[0]), "=r"(r[1]) : "r"(addr));
}
__device__ __forceinline__ void mma16816(float (&c)[4], const uint32_t (&a)[4],
                                         uint32_t b0, uint32_t b1) {
    asm volatile("mma.sync.aligned.m16n8k16.row.col.f32.f16.f16.f32 "
                 "{%0,%1,%2,%3}, {%4,%5,%6,%7}, {%8,%9}, {%0,%1,%2,%3};"
                 : "+f"(c[0]), "+f"(c[1]), "+f"(c[2]), "+f"(c[3])
                 : "r"(a[0]), "r"(a[1]), "r"(a[2]), "r"(a[3]), "r"(b0), "r"(b1));
}
#define CP_ASYNC16(dst, src) \
    asm volatile("cp.async.cg.shared.global [%0], [%1], 16;" :: "r"(dst), "l"(src))
#define CP_COMMIT() asm volatile("cp.async.commit_group;" ::: "memory")
#define CP_WAIT1()  asm volatile("cp.async.wait_group 1;" ::: "memory")
#define CP_WAIT0()  asm volatile("cp.async.wait_group 0;" ::: "memory")

// ================= scratch (static device globals; no allocation) =================
__device__ float g_xt[(size_t)MROWS * CH];
__device__ __align__(16) __half g_Ahi[(size_t)MROWS * KDIM];
__device__ __align__(16) __half g_Alo[(size_t)MROWS * KDIM];
__device__ __align__(16) __half g_Xhi[(size_t)MROWS * CH];
__device__ __align__(16) __half g_Whi[(size_t)3 * CH * KDIM];
__device__ __align__(16) __half g_Chi[(size_t)(CH / 2) * CH];
__device__ float g_y[(size_t)MROWS * CH];
__device__ int   g_idx[MROWS * KNN];
__device__ __align__(16) float g_sum[3 * CH];    // per-layer column sums
__device__ __align__(16) float g_sumsq[3 * CH];

__device__ __forceinline__ uint32_t pack_pair(float s, float m, float& sl, float& ml) {
    __half2 v;
    v.x = __float2half_rn(s);
    v.y = __float2half_rn(m);
    sl = s - __half2float(v.x);
    ml = m - __half2float(v.y);
    return *(uint32_t*)&v;
}
__device__ __forceinline__ uint32_t pack_lo(float sl, float ml) {
    __half2 v;
    v.x = __float2half_rn(sl);
    v.y = __float2half_rn(ml);
    return *(uint32_t*)&v;
}

#define LTC(da, ia, db, ib) ((da) < (db) || ((da) == (db) && (ia) < (ib)))
#define W_ELEMS (CH * KDIM)            // 524288
#define C_ELEMS ((CH / 2) * CH)        // 131072
#define NB_KNN  2048                   // (NPTS/8) * BATCH
#define NB_TR   8192                   // (NPTS/32)*(CH/32)*BATCH
#define NB_WS   ((3 * W_ELEMS + C_ELEMS) / 256)   // 6656

// ===== preamble: knn (blocks [0,2048)) | transpose | wsplit — one launch =========
__global__ void preamble_kernel(const float* __restrict__ x, const float* __restrict__ pos,
                                const float* __restrict__ w1, const float* __restrict__ w2,
                                const float* __restrict__ w3, const float* __restrict__ wc1) {
    __shared__ float sbuf[3 * NPTS];   // 48 KB, unioned across roles
    int bid = blockIdx.x, tid = threadIdx.x;

    if (bid < NB_KNN) {
        // ---------------- KNN (bit-exact vs reference; DO NOT TOUCH) -------------
        float* sx = sbuf;
        float* sy = sbuf + NPTS;
        float* sd = sbuf + 2 * NPTS;
        int b = bid >> 9;              // 512 q-blocks per batch
        int qb = bid & 511;
        const float* p = pos + (size_t)b * NPTS * 2;
        for (int j = tid; j < NPTS; j += 256) {
            float xx = p[2 * j], yy = p[2 * j + 1];
            sx[j] = xx; sy[j] = yy;
            sd[j] = __fadd_rn(__fmul_rn(xx, xx), __fmul_rn(yy, yy));  // add-form d2
        }
        __syncthreads();

        int warp = tid >> 5, lane = tid & 31;
        int q = qb * 8 + warp;

        float xi = sx[q], yi = sy[q], d2i = sd[q];
        const float INF = __int_as_float(0x7f800000);
        float d0 = INF, d1 = INF, d2 = INF, d3 = INF, d4 = INF;
        int   i0 = 0x7fffffff, i1 = 0x7fffffff, i2 = 0x7fffffff, i3 = 0x7fffffff, i4 = 0x7fffffff;

        for (int j = lane; j < NPTS; j += 32) {
            float dot  = __fmaf_rn(yi, sy[j], __fmul_rn(xi, sx[j]));  // fma-form dot
            float dist = __fadd_rn(__fadd_rn(d2i, sd[j]), -__fmul_rn(2.0f, dot));
            if (LTC(dist, j, d4, i4)) {
                d4 = dist; i4 = j;
                if (LTC(d4, i4, d3, i3)) { float tf = d3; d3 = d4; d4 = tf; int ti = i3; i3 = i4; i4 = ti; }
                if (LTC(d3, i3, d2, i2)) { float tf = d2; d2 = d3; d3 = tf; int ti = i2; i2 = i3; i3 = ti; }
                if (LTC(d2, i2, d1, i1)) { float tf = d1; d1 = d2; d2 = tf; int ti = i1; i1 = i2; i2 = ti; }
                if (LTC(d1, i1, d0, i0)) { float tf = d0; d0 = d1; d1 = tf; int ti = i0; i0 = i1; i1 = ti; }
            }
        }
#pragma unroll
        for (int k = 0; k < KNN; k++) {
            float od = d0; int oi = i0;
#pragma unroll
            for (int off = 16; off; off >>= 1) {
                float td = __shfl_down_sync(0xffffffffu, od, off);
                int   ti = __shfl_down_sync(0xffffffffu, oi, off);
                if (LTC(td, ti, od, oi)) { od = td; oi = ti; }
            }
            od = __shfl_sync(0xffffffffu, od, 0);
            oi = __shfl_sync(0xffffffffu, oi, 0);
            if (oi == i0) {
                d0 = d1; i0 = i1; d1 = d2; i1 = i2; d2 = d3; i2 = i3; d3 = d4; i3 = i4;
                d4 = INF; i4 = 0x7fffffff;
            }
            if (lane == 0) g_idx[((size_t)(b * NPTS + q)) * KNN + k] = oi;
        }
    } else if (bid < NB_KNN + NB_TR) {
        // ---------------- transpose: x [B,C,N] -> g_xt [B*N, C] ------------------
        float (*tile)[33] = (float(*)[33])sbuf;
        int i = bid - NB_KNN;
        int n0 = (i & 127) * 32;
        int c0 = ((i >> 7) & 15) * 32;
        int b = i >> 11;
        int tx = tid & 31, ty = tid >> 5;  // (32, 8)
#pragma unroll
        for (int k = 0; k < 4; k++) {
            int c = c0 + ty + k * 8;
            tile[ty + k * 8][tx] = x[((size_t)(b * CH + c)) * NPTS + n0 + tx];
        }
        __syncthreads();
#pragma unroll
        for (int k = 0; k < 4; k++) {
            int n = n0 + ty + k * 8;
            g_xt[((size_t)(b * NPTS + n)) * CH + c0 + tx] = tile[tx][ty + k * 8];
        }
    } else {
        // ---------------- weight fp16 conversion + stats zero --------------------
        int i = (bid - NB_KNN - NB_TR) * 256 + tid;
        if (i < 3 * CH) { g_sum[i] = 0.f; g_sumsq[i] = 0.f; }
        const float* src; __half* hi; int k;
        if (i < W_ELEMS)            { src = w1;  hi = g_Whi;               k = i; }
        else if (i < 2 * W_ELEMS)   { src = w2;  hi = g_Whi + W_ELEMS;     k = i - W_ELEMS; }
        else if (i < 3 * W_ELEMS)   { src = w3;  hi = g_Whi + 2 * W_ELEMS; k = i - 2 * W_ELEMS; }
        else                        { src = wc1; hi = g_Chi;               k = i - 3 * W_ELEMS; }
        hi[k] = __float2half_rn(src[k]);
    }
}

// ---------------- feat (layer 1): 1 row per 128-thread block, float4 -------------
__global__ void feat_kernel() {
    __shared__ int nb[KNN];
    int r = blockIdx.x, tid = threadIdx.x;
    if (tid < KNN) nb[tid] = (r >> 12) * NPTS + g_idx[r * KNN + tid];
    __syncthreads();
    float4 s = ((const float4*)(g_xt + (size_t)r * CH))[tid];
    float4 m = make_float4(-1e30f, -1e30f, -1e30f, -1e30f);
#pragma unroll
    for (int k = 0; k < KNN; k++) {
        float4 v = ((const float4*)(g_xt + (size_t)nb[k] * CH))[tid];
        m.x = fmaxf(m.x, v.x - s.x); m.y = fmaxf(m.y, v.y - s.y);
        m.z = fmaxf(m.z, v.z - s.z); m.w = fmaxf(m.w, v.w - s.w);
    }
    float slx, mlx, sly, mly, slz, mlz, slw, mlw;
    uint4 hi, lo;
    hi.x = pack_pair(s.x, m.x, slx, mlx);
    hi.y = pack_pair(s.y, m.y, sly, mly);
    hi.z = pack_pair(s.z, m.z, slz, mlz);
    hi.w = pack_pair(s.w, m.w, slw, mlw);
    lo.x = pack_lo(slx, mlx); lo.y = pack_lo(sly, mly);
    lo.z = pack_lo(slz, mlz); lo.w = pack_lo(slw, mlw);
    ((uint4*)(g_Ahi + (size_t)r * KDIM))[tid] = hi;
    ((uint4*)(g_Alo + (size_t)r * KDIM))[tid] = lo;
}

// ---- bnfeat (layers 2,3): inline BN coefs from per-layer stats, gather+maxrel ----
__global__ void bnfeat_kernel(const float* __restrict__ gamma, const float* __restrict__ beta,
                              const float* __restrict__ gsum, const float* __restrict__ gsumsq) {
    __shared__ int nb[KNN];
    int r = blockIdx.x, tid = threadIdx.x;
    if (tid < KNN) nb[tid] = (r >> 12) * NPTS + g_idx[r * KNN + tid];
    __syncthreads();
    const float inv = 1.0f / (float)MROWS;
    float4 sm = ((const float4*)gsum)[tid];
    float4 sq = ((const float4*)gsumsq)[tid];
    float4 gm = ((const float4*)gamma)[tid];
    float4 bt = ((const float4*)beta)[tid];
    float4 a, b;
    {
        float mean;
        mean = sm.x * inv; a.x = rsqrtf(sq.x * inv - mean * mean + 1e-5f) * gm.x; b.x = bt.x - mean * a.x;
        mean = sm.y * inv; a.y = rsqrtf(sq.y * inv - mean * mean + 1e-5f) * gm.y; b.y = bt.y - mean * a.y;
        mean = sm.z * inv; a.z = rsqrtf(sq.z * inv - mean * mean + 1e-5f) * gm.z; b.z = bt.z - mean * a.z;
        mean = sm.w * inv; a.w = rsqrtf(sq.w * inv - mean * mean + 1e-5f) * gm.w; b.w = bt.w - mean * a.w;
    }
    float4 y = ((const float4*)(g_y + (size_t)r * CH))[tid];
    float4 s;
    s.x = fmaxf(fmaf(y.x, a.x, b.x), 0.f);
    s.y = fmaxf(fmaf(y.y, a.y, b.y), 0.f);
    s.z = fmaxf(fmaf(y.z, a.z, b.z), 0.f);
    s.w = fmaxf(fmaf(y.w, a.w, b.w), 0.f);
    float4 m = make_float4(-1e30f, -1e30f, -1e30f, -1e30f);
#pragma unroll
    for (int k = 0; k < KNN; k++) {
        float4 v = ((const float4*)(g_y + (size_t)nb[k] * CH))[tid];
        m.x = fmaxf(m.x, fmaxf(fmaf(v.x, a.x, b.x), 0.f) - s.x);
        m.y = fmaxf(m.y, fmaxf(fmaf(v.y, a.y, b.y), 0.f) - s.y);
        m.z = fmaxf(m.z, fmaxf(fmaf(v.z, a.z, b.z), 0.f) - s.z);
        m.w = fmaxf(m.w, fmaxf(fmaf(v.w, a.w, b.w), 0.f) - s.w);
    }
    float slx, mlx, sly, mly, slz, mlz, slw, mlw;
    uint4 hi, lo;
    hi.x = pack_pair(s.x, m.x, slx, mlx);
    hi.y = pack_pair(s.y, m.y, sly, mly);
    hi.z = pack_pair(s.z, m.z, slz, mlz);
    hi.w = pack_pair(s.w, m.w, slw, mlw);
    lo.x = pack_lo(slx, mlx); lo.y = pack_lo(sly, mly);
    lo.z = pack_lo(slz, mlz); lo.w = pack_lo(slw, mlw);
    ((uint4*)(g_Ahi + (size_t)r * KDIM))[tid] = hi;
    ((uint4*)(g_Alo + (size_t)r * KDIM))[tid] = lo;
}

// ---- bn_apply_cls: inline coefs from layer-3 stats, g_y -> Xhi (fp16), float4 ---
__global__ void bn_apply_cls(const float* __restrict__ gamma, const float* __restrict__ beta,
                             const float* __restrict__ gsum, const float* __restrict__ gsumsq) {
    int i4 = blockIdx.x * blockDim.x + threadIdx.x;   // float4 index
    int c4 = i4 & 127;
    const float inv = 1.0f / (float)MROWS;
    float4 sm = ((const float4*)gsum)[c4];
    float4 sq = ((const float4*)gsumsq)[c4];
    float4 gm = ((const float4*)gamma)[c4];
    float4 bt = ((const float4*)beta)[c4];
    float4 a, b;
    {
        float mean;
        mean = sm.x * inv; a.x = rsqrtf(sq.x * inv - mean * mean + 1e-5f) * gm.x; b.x = bt.x - mean * a.x;
        mean = sm.y * inv; a.y = rsqrtf(sq.y * inv - mean * mean + 1e-5f) * gm.y; b.y = bt.y - mean * a.y;
        mean = sm.z * inv; a.z = rsqrtf(sq.z * inv - mean * mean + 1e-5f) * gm.z; b.z = bt.z - mean * a.z;
        mean = sm.w * inv; a.w = rsqrtf(sq.w * inv - mean * mean + 1e-5f) * gm.w; b.w = bt.w - mean * a.w;
    }
    float4 y = ((const float4*)g_y)[i4];
    float vx = fmaxf(fmaf(y.x, a.x, b.x), 0.f);
    float vy = fmaxf(fmaf(y.y, a.y, b.y), 0.f);
    float vz = fmaxf(fmaf(y.z, a.z, b.z), 0.f);
    float vw = fmaxf(fmaf(y.w, a.w, b.w), 0.f);
    __half2 h0; h0.x = __float2half_rn(vx); h0.y = __float2half_rn(vy);
    __half2 h1; h1.x = __float2half_rn(vz); h1.y = __float2half_rn(vw);
    uint2 hv = make_uint2(*(uint32_t*)&h0, *(uint32_t*)&h1);
    ((uint2*)g_Xhi)[i4] = hv;
}

// ============ HMMA fp16 fused-term GEMM (mr layers), 128x128, 2-stage, 2 CTA/SM ==
// C = (Ahi + Alo)*Bh^T + bias; fused column stats into per-layer arrays.
#define MR_STG (3 * 16384)

__global__ void __launch_bounds__(256, 2) mma_gemm(
    const __half* __restrict__ Ahi, const __half* __restrict__ Alo,
    const __half* __restrict__ Bh, const float* __restrict__ bias,
    float* __restrict__ C, float* __restrict__ gsum, float* __restrict__ gsumsq) {
    const int Kd = KDIM, Nn = CH;
    extern __shared__ char smem[];
    uint32_t sb = smem_u32(smem);
    int tid = threadIdx.x, lane = tid & 31, wid = tid >> 5;
    int wm = wid & 1, wn = wid >> 1;
    int row0 = blockIdx.y * 128, col0 = blockIdx.x * 128;
    const int NIT = Kd >> 6;

    float acc[4][4][4];
#pragma unroll
    for (int mi = 0; mi < 4; mi++)
#pragma unroll
        for (int ni = 0; ni < 4; ni++)
#pragma unroll
            for (int j = 0; j < 4; j++) acc[mi][ni][j] = 0.f;

    int lr = tid >> 3, lg = tid & 7;

    auto load_chunk = [&](int kc, int st) {
        uint32_t abase = sb + st * MR_STG;
        uint32_t lbase = abase + 16384;
        uint32_t bbase = abase + 32768;
#pragma unroll
        for (int i = 0; i < 4; i++) {
            int r = lr + i * 32;
            CP_ASYNC16(abase + SWZ((uint32_t)(r * 128 + lg * 16)),
                       Ahi + (size_t)(row0 + r) * Kd + kc * 64 + lg * 8);
        }
#pragma unroll
        for (int i = 0; i < 4; i++) {
            int r = lr + i * 32;
            CP_ASYNC16(lbase + SWZ((uint32_t)(r * 128 + lg * 16)),
                       Alo + (size_t)(row0 + r) * Kd + kc * 64 + lg * 8);
        }
#pragma unroll
        for (int i = 0; i < 4; i++) {
            int r = lr + i * 32;
            CP_ASYNC16(bbase + SWZ((uint32_t)(r * 128 + lg * 16)),
                       Bh + (size_t)(col0 + r) * Kd + kc * 64 + lg * 8);
        }
        CP_COMMIT();
    };

    load_chunk(0, 0);
    load_chunk(1, 1);

    for (int it = 0; it < NIT; it++) {
        int s = it & 1;
        if (it + 1 < NIT) { CP_WAIT1(); } else { CP_WAIT0(); }
        __syncthreads();

        uint32_t abase = sb + s * MR_STG;
        uint32_t bbase = abase + 32768;
#pragma unroll
        for (int kk = 0; kk < 4; kk++) {
            uint32_t bfr[4][2];
#pragma unroll
            for (int ni = 0; ni < 4; ni++) {
                int r = wn * 32 + ni * 8 + (lane & 7);
                uint32_t off = (uint32_t)(r * 128 + kk * 32 + ((lane >> 3) & 1) * 16);
                ldsm_x2(bfr[ni], bbase + SWZ(off));
            }
#pragma unroll
            for (int t = 0; t < 2; t++) {
                uint32_t tbase = abase + t * 16384;
                uint32_t af[4][4];
#pragma unroll
                for (int mi = 0; mi < 4; mi++) {
                    int r = wm * 64 + mi * 16 + (lane & 15);
                    uint32_t off = (uint32_t)(r * 128 + kk * 32 + (lane >> 4) * 16);
                    ldsm_x4(af[mi], tbase + SWZ(off));
                }
#pragma unroll
                for (int ni = 0; ni < 4; ni++)
#pragma unroll
                    for (int mi = 0; mi < 4; mi++)
                        mma16816(acc[mi][ni], af[mi], bfr[ni][0], bfr[ni][1]);
            }
        }
        __syncthreads();
        if (it + 2 < NIT) load_chunk(it + 2, s);
    }

    // epilogue: +bias, store, fused column stats
    float s_[4][2], q_[4][2];
#pragma unroll
    for (int ni = 0; ni < 4; ni++) { s_[ni][0] = s_[ni][1] = q_[ni][0] = q_[ni][1] = 0.f; }
#pragma unroll
    for (int mi = 0; mi < 4; mi++) {
        int row = row0 + wm * 64 + mi * 16 + (lane >> 2);
#pragma unroll
        for (int ni = 0; ni < 4; ni++) {
            int col = col0 + wn * 32 + ni * 8 + (lane & 3) * 2;
            float b0 = bias[col], b1 = bias[col + 1];
            float v0 = acc[mi][ni][0] + b0, v1 = acc[mi][ni][1] + b1;
            float v2 = acc[mi][ni][2] + b0, v3 = acc[mi][ni][3] + b1;
            s_[ni][0] += v0 + v2; s_[ni][1] += v1 + v3;
            q_[ni][0] += v0 * v0 + v2 * v2; q_[ni][1] += v1 * v1 + v3 * v3;
            *(float2*)(C + (size_t)row * Nn + col) = make_float2(v0, v1);
            *(float2*)(C + (size_t)(row + 8) * Nn + col) = make_float2(v2, v3);
        }
    }
#pragma unroll
    for (int ni = 0; ni < 4; ni++) {
#pragma unroll
        for (int j = 0; j < 2; j++) {
#pragma unroll
            for (int off = 4; off <= 16; off <<= 1) {
                s_[ni][j] += __shfl_xor_sync(0xffffffffu, s_[ni][j], off);
                q_[ni][j] += __shfl_xor_sync(0xffffffffu, q_[ni][j], off);
            }
        }
    }
    if ((lane >> 2) == 0) {
#pragma unroll
        for (int ni = 0; ni < 4; ni++) {
            int col = col0 + wn * 32 + ni * 8 + (lane & 3) * 2;
            atomicAdd(&gsum[col],     s_[ni][0]);
            atomicAdd(&gsum[col + 1], s_[ni][1]);
            atomicAdd(&gsumsq[col],     q_[ni][0]);
            atomicAdd(&gsumsq[col + 1], q_[ni][1]);
        }
    }
}

// ===== cls_final: out = relu(Xhi @ Chi^T + bc1) @ Wc2^T + bc2, fused ============
// 128x256 tile (full N), grid 128 CTAs, 1 CTA/SM. 8 warps (2M x 4N), warp 64x64.
// Mainloop 2-stage: A 16KB + B 32KB per stage. Epilogue: h (fp32) in smem,
// then per-warp reduction against Wc2.
#define CLS_STG (3 * 16384)                 // 48 KB/stage
#define H_PITCH 257
#define CLSF_SMEM (128 * H_PITCH * 4 + 5 * 256 * 4)   // 136704 > 2*CLS_STG

__global__ void __launch_bounds__(256, 1) cls_final(
    const __half* __restrict__ Xhi, const __half* __restrict__ Bh,
    const float* __restrict__ bc1, const float* __restrict__ Wc2,
    const float* __restrict__ bc2, float* __restrict__ out) {
    const int Kd = CH;
    extern __shared__ char smem[];
    uint32_t sb = smem_u32(smem);
    int tid = threadIdx.x, lane = tid & 31, wid = tid >> 5;
    int wm = wid & 1, wn = wid >> 1;     // warp tile 64 x 64
    int row0 = blockIdx.x * 128;
    const int NIT = Kd >> 6;             // 8

    float acc[4][8][4];
#pragma unroll
    for (int mi = 0; mi < 4; mi++)
#pragma unroll
        for (int ni = 0; ni < 8; ni++)
#pragma unroll
            for (int j = 0; j < 4; j++) acc[mi][ni][j] = 0.f;

    int lr = tid >> 3, lg = tid & 7;

    auto load_chunk = [&](int kc, int st) {
        uint32_t abase = sb + st * CLS_STG;
        uint32_t bbase = abase + 16384;
#pragma unroll
        for (int i = 0; i < 4; i++) {
            int r = lr + i * 32;
            CP_ASYNC16(abase + SWZ((uint32_t)(r * 128 + lg * 16)),
                       Xhi + (size_t)(row0 + r) * Kd + kc * 64 + lg * 8);
        }
#pragma unroll
        for (int i = 0; i < 8; i++) {
            int r = lr + i * 32;
            CP_ASYNC16(bbase + SWZ((uint32_t)(r * 128 + lg * 16)),
                       Bh + (size_t)r * Kd + kc * 64 + lg * 8);
        }
        CP_COMMIT();
    };

    load_chunk(0, 0);
    load_chunk(1, 1);

    for (int it = 0; it < NIT; it++) {
        int s = it & 1;
        if (it + 1 < NIT) { CP_WAIT1(); } else { CP_WAIT0(); }
        __syncthreads();

        uint32_t abase = sb + s * CLS_STG;
        uint32_t bbase = abase + 16384;
#pragma unroll
        for (int kk = 0; kk < 4; kk++) {
            uint32_t af[4][4];
#pragma unroll
            for (int mi = 0; mi < 4; mi++) {
                int r = wm * 64 + mi * 16 + (lane & 15);
                uint32_t off = (uint32_t)(r * 128 + kk * 32 + (lane >> 4) * 16);
                ldsm_x4(af[mi], abase + SWZ(off));
            }
#pragma unroll
            for (int p = 0; p < 4; p++) {
                uint32_t bf[4];
                int r = wn * 64 + p * 16 + (lane & 15);
                uint32_t off = (uint32_t)(r * 128 + kk * 32 + (lane >> 4) * 16);
                ldsm_x4(bf, bbase + SWZ(off));
#pragma unroll
                for (int mi = 0; mi < 4; mi++) {
                    mma16816(acc[mi][2 * p], af[mi], bf[0], bf[2]);
                    mma16816(acc[mi][2 * p + 1], af[mi], bf[1], bf[3]);
                }
            }
        }
        __syncthreads();
        if (it + 2 < NIT) load_chunk(it + 2, s);
    }

    // ---- h (fp32) -> smem, then reduce against Wc2 ----
    float* hs = (float*)smem;               // [128][H_PITCH]
    float* wsm = (float*)smem + 128 * H_PITCH;  // [5][256]
    __syncthreads();
#pragma unroll
    for (int mi = 0; mi < 4; mi++) {
        int row = wm * 64 + mi * 16 + (lane >> 2);
#pragma unroll
        for (int ni = 0; ni < 8; ni++) {
            int col = wn * 64 + ni * 8 + (lane & 3) * 2;
            float b0 = bc1[col], b1 = bc1[col + 1];
            hs[row * H_PITCH + col]           = fmaxf(acc[mi][ni][0] + b0, 0.f);
            hs[row * H_PITCH + col + 1]       = fmaxf(acc[mi][ni][1] + b1, 0.f);
            hs[(row + 8) * H_PITCH + col]     = fmaxf(acc[mi][ni][2] + b0, 0.f);
            hs[(row + 8) * H_PITCH + col + 1] = fmaxf(acc[mi][ni][3] + b1, 0.f);
        }
    }
    for (int i = tid; i < 5 * 256; i += 256) wsm[i] = Wc2[i];
    __syncthreads();

    float bv0 = bc2[0], bv1 = bc2[1], bv2 = bc2[2], bv3 = bc2[3], bv4 = bc2[4];
#pragma unroll
    for (int rr = 0; rr < 16; rr++) {
        int row = wid * 16 + rr;
        const float* hp = hs + row * H_PITCH + lane * 8;
        float a0 = 0, a1 = 0, a2 = 0, a3 = 0, a4 = 0;
#pragma unroll
        for (int c = 0; c < 8; c++) {
            float hv = hp[c];
            int wc = lane * 8 + c;
            a0 = fmaf(hv, wsm[0 * 256 + wc], a0);
            a1 = fmaf(hv, wsm[1 * 256 + wc], a1);
            a2 = fmaf(hv, wsm[2 * 256 + wc], a2);
            a3 = fmaf(hv, wsm[3 * 256 + wc], a3);
            a4 = fmaf(hv, wsm[4 * 256 + wc], a4);
        }
#pragma unroll
        for (int off = 16; off; off >>= 1) {
            a0 += __shfl_xor_sync(0xffffffffu, a0, off);
            a1 += __shfl_xor_sync(0xffffffffu, a1, off);
            a2 += __shfl_xor_sync(0xffffffffu, a2, off);
            a3 += __shfl_xor_sync(0xffffffffu, a3, off);
            a4 += __shfl_xor_sync(0xffffffffu, a4, off);
        }
        if (lane == 0) {
            float* o = out + (size_t)(row0 + row) * 5;
            o[0] = a0 + bv0; o[1] = a1 + bv1; o[2] = a2 + bv2;
            o[3] = a3 + bv3; o[4] = a4 + bv4;
        }
    }
}

// ---------------- launch ----------------
extern "C" void kernel_launch(void* const* d_in, const int* in_sizes, int n_in,
                              void* d_out, int out_size) {
    const float* x    = (const float*)d_in[0];
    const float* pos  = (const float*)d_in[1];
    const float* W[3]  = {(const float*)d_in[2], (const float*)d_in[6], (const float*)d_in[10]};
    const float* bb[3] = {(const float*)d_in[3], (const float*)d_in[7], (const float*)d_in[11]};
    const float* gg[3] = {(const float*)d_in[4], (const float*)d_in[8], (const float*)d_in[12]};
    const float* be[3] = {(const float*)d_in[5], (const float*)d_in[9], (const float*)d_in[13]};
    const float* Wc1 = (const float*)d_in[14];
    const float* bc1 = (const float*)d_in[15];
    const float* Wc2 = (const float*)d_in[16];
    const float* bc2 = (const float*)d_in[17];
    float* out = (float*)d_out;

    float *p_y, *p_sum, *p_sumsq;
    __half *p_Ahi, *p_Alo, *p_Xhi, *p_Whi, *p_Chi;
    cudaGetSymbolAddress((void**)&p_y, g_y);
    cudaGetSymbolAddress((void**)&p_sum, g_sum);
    cudaGetSymbolAddress((void**)&p_sumsq, g_sumsq);
    cudaGetSymbolAddress((void**)&p_Ahi, g_Ahi);
    cudaGetSymbolAddress((void**)&p_Alo, g_Alo);
    cudaGetSymbolAddress((void**)&p_Xhi, g_Xhi);
    cudaGetSymbolAddress((void**)&p_Whi, g_Whi);
    cudaGetSymbolAddress((void**)&p_Chi, g_Chi);

    cudaFuncSetAttribute(mma_gemm, cudaFuncAttributeMaxDynamicSharedMemorySize, 2 * MR_STG);
    cudaFuncSetAttribute(cls_final, cudaFuncAttributeMaxDynamicSharedMemorySize, CLSF_SMEM);

    preamble_kernel<<<NB_KNN + NB_TR + NB_WS, 256>>>(x, pos, W[0], W[1], W[2], Wc1);

    for (int i = 0; i < 3; i++) {
        if (i == 0) feat_kernel<<<MROWS, 128>>>();
        else        bnfeat_kernel<<<MROWS, 128>>>(gg[i - 1], be[i - 1],
                                                  p_sum + (i - 1) * CH, p_sumsq + (i - 1) * CH);
        mma_gemm<<<dim3(CH / 128, MROWS / 128), 256, 2 * MR_STG>>>(
            p_Ahi, p_Alo, p_Whi + (size_t)i * CH * KDIM, bb[i], p_y,
            p_sum + i * CH, p_sumsq + i * CH);
    }

    // classifier + final, fused
    bn_apply_cls<<<(MROWS * CH / 4) / 256, 256>>>(gg[2], be[2], p_sum + 2 * CH, p_sumsq + 2 * CH);
    cls_final<<<MROWS / 128, 256, CLSF_SMEM>>>(p_Xhi, p_Chi, bc1, Wc2, bc2, out);
}